// round 6
// baseline (speedup 1.0000x reference)
#include <cuda_runtime.h>
#include <math.h>

#define NB 16
#define NT 2048
#define ROWS_PER_CTA 8
#define THREADS 256
#define NWARPS (THREADS / 32)

// Scratch for sigmoid(logits); __device__ global (no allocation).
__device__ __align__(16) float g_scores[NB * NT];

__global__ void sigmoid_kernel(const float* __restrict__ logits, int n) {
    int idx = blockIdx.x * blockDim.x + threadIdx.x;
    if (idx < n) {
        float x = logits[idx];
        g_scores[idx] = 1.0f / (1.0f + expf(-x));
    }
}

__device__ __forceinline__ float tanh_fast(float x) {
    float y;
    asm("tanh.approx.f32 %0, %1;" : "=f"(y) : "f"(x));
    return y;
}

__global__ void __launch_bounds__(THREADS)
pairwise_softmax_kernel(const int* __restrict__ seq_len, float* __restrict__ out) {
    __shared__ __align__(16) float s_s[NT];
    __shared__ float s_red[2][NWARPS];

    const int cta_per_b = NT / ROWS_PER_CTA;  // 256
    const int b = blockIdx.x / cta_per_b;
    const int rowBase = (blockIdx.x % cta_per_b) * ROWS_PER_CTA;
    const int L = __ldg(seq_len + b);
    const int tid = threadIdx.x;
    const int warp = tid >> 5;
    const int lane = tid & 31;

    float* outBase = out + ((size_t)b * NT + rowBase) * NT;

    // Fast path: whole 8-row group is past seq_len -> pure zero stores.
    if (rowBase >= L) {
        float4 z = make_float4(0.f, 0.f, 0.f, 0.f);
        float4* o = (float4*)outBase;
#pragma unroll
        for (int k = 0; k < (ROWS_PER_CTA * NT / 4) / THREADS; k++)
            __stcs(o + tid + k * THREADS, z);
        return;
    }

    // Stage this batch's score row into shared memory (once per 8 rows).
    {
        const float4* src = (const float4*)(g_scores + b * NT);
        float4* dst = (float4*)s_s;
#pragma unroll
        for (int k = 0; k < (NT / 4) / THREADS; k++)
            dst[tid + k * THREADS] = __ldg(src + tid + k * THREADS);
        __syncthreads();
    }

    // e^{0.5 + 0.5 t} = sum_k (e^{0.5} * 0.5^k / k!) t^k, |t| <= 1, err ~3.6e-5
    const float c0 = 1.64872127f;
    const float c1 = 0.824360635f;
    const float c2 = 0.206090159f;
    const float c3 = 0.0343483598f;
    const float c4 = 0.00429354498f;
    const float c5 = 4.29354498e-4f;

    for (int r = 0; r < ROWS_PER_CTA; r++) {
        const int i = rowBase + r;
        float* orow = outBase + (size_t)r * NT;

        if (i >= L) {  // CTA-uniform branch (all threads together)
            float4 z = make_float4(0.f, 0.f, 0.f, 0.f);
            float4* o = (float4*)orow;
#pragma unroll
            for (int k = 0; k < (NT / 4) / THREADS; k++)
                __stcs(o + tid + k * THREADS, z);
            continue;
        }

        const float si = s_s[i];
        float e[2][4];
        float sum = 0.f;

#pragma unroll
        for (int k = 0; k < 2; k++) {
            const int j4 = tid + k * THREADS;
            float4 sj = ((const float4*)s_s)[j4];
            float vs[4] = {sj.x, sj.y, sj.z, sj.w};
            const int jb = 4 * j4;
#pragma unroll
            for (int m = 0; m < 4; m++) {
                float u = fabsf(si - vs[m]);
                float z = fmaf(u, -5.0f, 2.5f);     // tanh arg: 5*(0.5-u)
                float t = tanh_fast(z);              // sigmoid = 0.5t+0.5
                float p = fmaf(c5, t, c4);           // exp(sigmoid) poly in t
                p = fmaf(p, t, c3);
                p = fmaf(p, t, c2);
                p = fmaf(p, t, c1);
                p = fmaf(p, t, c0);
                float ev = (jb + m < L) ? p : 0.0f;  // masked cols -> 0
                e[k][m] = ev;
                sum += ev;
            }
        }

        // Warp reduce + double-buffered cross-warp reduce (1 barrier / row).
#pragma unroll
        for (int o = 16; o > 0; o >>= 1)
            sum += __shfl_xor_sync(0xffffffffu, sum, o);
        if (lane == 0) s_red[r & 1][warp] = sum;
        __syncthreads();
        float tot = 0.f;
#pragma unroll
        for (int w = 0; w < NWARPS; w++) tot += s_red[r & 1][w];
        const float inv = __frcp_rn(tot);

#pragma unroll
        for (int k = 0; k < 2; k++) {
            float4 o;
            o.x = e[k][0] * inv;
            o.y = e[k][1] * inv;
            o.z = e[k][2] * inv;
            o.w = e[k][3] * inv;
            __stcs((float4*)orow + tid + k * THREADS, o);
        }
    }
}

extern "C" void kernel_launch(void* const* d_in, const int* in_sizes, int n_in,
                              void* d_out, int out_size) {
    const float* logits = (const float*)d_in[0];   // [16, 2048, 1] f32
    const int* seq_len = (const int*)d_in[1];      // [16] i32
    float* out = (float*)d_out;                    // [16, 2048, 2048] f32

    sigmoid_kernel<<<(NB * NT + 255) / 256, 256>>>(logits, NB * NT);
    pairwise_softmax_kernel<<<NB * (NT / ROWS_PER_CTA), THREADS>>>(seq_len, out);
}

// round 9
// speedup vs baseline: 1.0015x; 1.0015x over previous
#include <cuda_runtime.h>
#include <math.h>

#define NB 16
#define NT 2048
#define ROWS_PER_CTA 8
#define THREADS 256
#define NWARPS (THREADS / 32)

__device__ __forceinline__ float tanh_fast(float x) {
    float y;
    asm("tanh.approx.f32 %0, %1;" : "=f"(y) : "f"(x));
    return y;
}

// Fully fused: each CTA computes sigmoid(logits[b,:]) into smem itself
// (redundant across CTAs but cheap — 8 expf/thread, hidden under the 256MB
// store stream; logits stay resident in L2), then does 8 rows of
// pairwise-relevance masked softmax.
__global__ void __launch_bounds__(THREADS, 8)
pairwise_softmax_kernel(const float* __restrict__ logits,
                        const int* __restrict__ seq_len,
                        float* __restrict__ out) {
    __shared__ __align__(16) float s_s[NT];
    __shared__ float s_red[2][NWARPS];

    const int cta_per_b = NT / ROWS_PER_CTA;  // 256
    const int b = blockIdx.x / cta_per_b;
    const int rowBase = (blockIdx.x % cta_per_b) * ROWS_PER_CTA;
    const int L = __ldg(seq_len + b);
    const int tid = threadIdx.x;
    const int warp = tid >> 5;
    const int lane = tid & 31;

    float* outBase = out + ((size_t)b * NT + rowBase) * NT;

    // Fast path: whole 8-row group past seq_len -> pure zero stores.
    // CTA-uniform branch, so no barrier divergence.
    if (rowBase >= L) {
        float4 z = make_float4(0.f, 0.f, 0.f, 0.f);
        float4* o = (float4*)outBase;
#pragma unroll
        for (int k = 0; k < (ROWS_PER_CTA * NT / 4) / THREADS; k++)
            __stcs(o + tid + k * THREADS, z);
        return;
    }

    // Compute sigmoid(logits) for this batch row directly into smem.
    {
        const float* src = logits + b * NT;
#pragma unroll
        for (int k = 0; k < NT / THREADS; k++) {
            int idx = tid + k * THREADS;
            float x = __ldg(src + idx);
            s_s[idx] = 1.0f / (1.0f + expf(-x));
        }
    }
    __syncthreads();

    // e^{0.5 + 0.5 t} = sum_k (e^{0.5} * 0.5^k / k!) t^k, |t| <= 1, err ~3.6e-5
    const float c0 = 1.64872127f;
    const float c1 = 0.824360635f;
    const float c2 = 0.206090159f;
    const float c3 = 0.0343483598f;
    const float c4 = 0.00429354498f;
    const float c5 = 4.29354498e-4f;

    for (int r = 0; r < ROWS_PER_CTA; r++) {
        const int i = rowBase + r;
        float* orow = outBase + (size_t)r * NT;

        if (i >= L) {  // CTA-uniform branch
            float4 z = make_float4(0.f, 0.f, 0.f, 0.f);
            float4* o = (float4*)orow;
#pragma unroll
            for (int k = 0; k < (NT / 4) / THREADS; k++)
                __stcs(o + tid + k * THREADS, z);
            continue;
        }

        const float si = s_s[i];
        float e[2][4];
        float sum = 0.f;

#pragma unroll
        for (int k = 0; k < 2; k++) {
            const int j4 = tid + k * THREADS;
            float4 sj = ((const float4*)s_s)[j4];
            float vs[4] = {sj.x, sj.y, sj.z, sj.w};
            const int jb = 4 * j4;
#pragma unroll
            for (int m = 0; m < 4; m++) {
                float u = fabsf(si - vs[m]);
                float z = fmaf(u, -5.0f, 2.5f);     // tanh arg: 5*(0.5-u)
                float t = tanh_fast(z);              // sigmoid = 0.5t+0.5
                float p = fmaf(c5, t, c4);           // exp(sigmoid) poly in t
                p = fmaf(p, t, c3);
                p = fmaf(p, t, c2);
                p = fmaf(p, t, c1);
                p = fmaf(p, t, c0);
                float ev = (jb + m < L) ? p : 0.0f;  // masked cols -> 0
                e[k][m] = ev;
                sum += ev;
            }
        }

        // Warp reduce + double-buffered cross-warp reduce (1 barrier / row).
#pragma unroll
        for (int o = 16; o > 0; o >>= 1)
            sum += __shfl_xor_sync(0xffffffffu, sum, o);
        if (lane == 0) s_red[r & 1][warp] = sum;
        __syncthreads();
        float tot = 0.f;
#pragma unroll
        for (int w = 0; w < NWARPS; w++) tot += s_red[r & 1][w];
        const float inv = __frcp_rn(tot);

#pragma unroll
        for (int k = 0; k < 2; k++) {
            float4 o;
            o.x = e[k][0] * inv;
            o.y = e[k][1] * inv;
            o.z = e[k][2] * inv;
            o.w = e[k][3] * inv;
            __stcs((float4*)orow + tid + k * THREADS, o);
        }
    }
}

extern "C" void kernel_launch(void* const* d_in, const int* in_sizes, int n_in,
                              void* d_out, int out_size) {
    const float* logits = (const float*)d_in[0];   // [16, 2048, 1] f32
    const int* seq_len = (const int*)d_in[1];      // [16] i32
    float* out = (float*)d_out;                    // [16, 2048, 2048] f32

    pairwise_softmax_kernel<<<NB * (NT / ROWS_PER_CTA), THREADS>>>(logits, seq_len, out);
}

// round 10
// speedup vs baseline: 1.0180x; 1.0165x over previous
#include <cuda_runtime.h>

#define NB 16
#define NT 2048
#define ROWS_PER_CTA 8
#define THREADS 256
#define NWARPS (THREADS / 32)

__device__ __forceinline__ float tanh_fast(float x) {
    float y;
    asm("tanh.approx.f32 %0, %1;" : "=f"(y) : "f"(x));
    return y;
}

// e^{0.5 + 0.5 t} Taylor in t around 0, |t|<=1, abs err ~3.6e-5
#define C0 1.64872127f
#define C1 0.824360635f
#define C2 0.206090159f
#define C3 0.0343483598f
#define C4 0.00429354498f
#define C5 4.29354498e-4f

// Compute one row's 8 e-values + this thread's partial sum.
// Returns 0 / zeros for rows past L (caller stores zeros there).
__device__ __forceinline__ float compute_row(const float* __restrict__ s_s,
                                             int i, int L, int tid,
                                             float e[8]) {
    if (i >= L) {
#pragma unroll
        for (int q = 0; q < 8; q++) e[q] = 0.f;
        return 0.f;
    }
    const float si = s_s[i];
    float sum = 0.f;
#pragma unroll
    for (int k = 0; k < 2; k++) {
        const int j4 = tid + k * THREADS;
        float4 sj = ((const float4*)s_s)[j4];
        float vs[4] = {sj.x, sj.y, sj.z, sj.w};
        const int jb = 4 * j4;
#pragma unroll
        for (int m = 0; m < 4; m++) {
            float u = fabsf(si - vs[m]);
            float z = fmaf(u, -5.0f, 2.5f);   // 5*(0.5-u) = tanh arg
            float t = tanh_fast(z);           // sigmoid = 0.5t+0.5
            float p = fmaf(C5, t, C4);        // exp(sigmoid) poly in t
            p = fmaf(p, t, C3);
            p = fmaf(p, t, C2);
            p = fmaf(p, t, C1);
            p = fmaf(p, t, C0);
            float ev = (jb + m < L) ? p : 0.0f;
            e[k * 4 + m] = ev;
            sum += ev;
        }
    }
    return sum;
}

__global__ void __launch_bounds__(THREADS, 6)
pairwise_softmax_kernel(const float* __restrict__ logits,
                        const int* __restrict__ seq_len,
                        float* __restrict__ out) {
    __shared__ __align__(16) float s_s[NT];
    __shared__ float s_red[2][NWARPS];

    const int cta_per_b = NT / ROWS_PER_CTA;  // 256
    const int b = blockIdx.x / cta_per_b;
    const int rowBase = (blockIdx.x % cta_per_b) * ROWS_PER_CTA;
    const int L = __ldg(seq_len + b);
    const int tid = threadIdx.x;
    const int warp = tid >> 5;
    const int lane = tid & 31;

    float* outBase = out + ((size_t)b * NT + rowBase) * NT;

    // Fast path: whole 8-row group past seq_len -> pure zero stores.
    if (rowBase >= L) {
        float4 z = make_float4(0.f, 0.f, 0.f, 0.f);
        float4* o = (float4*)outBase;
#pragma unroll
        for (int k = 0; k < (ROWS_PER_CTA * NT / 4) / THREADS; k++)
            __stcs(o + tid + k * THREADS, z);
        return;
    }

    // Cheap prologue: sigmoid(x) = 0.5*tanh(x/2)+0.5, one MUFU per element.
    {
        const float* src = logits + b * NT;
#pragma unroll
        for (int k = 0; k < NT / THREADS; k++) {
            int idx = tid + k * THREADS;
            float x = __ldg(src + idx);
            s_s[idx] = fmaf(0.5f, tanh_fast(0.5f * x), 0.5f);
        }
    }
    __syncthreads();

    // Pipeline prologue: row 0's e-values and partial sum.
    float e_cur[8], e_next[8];
    {
        float ps = compute_row(s_s, rowBase, L, tid, e_cur);
#pragma unroll
        for (int o = 16; o > 0; o >>= 1)
            ps += __shfl_xor_sync(0xffffffffu, ps, o);
        if (lane == 0) s_red[0][warp] = ps;
    }
    __syncthreads();

#pragma unroll
    for (int r = 0; r < ROWS_PER_CTA; r++) {
        const int i = rowBase + r;
        float* orow = outBase + (size_t)r * NT;

        // 1. Row sum is ready (barriered last iteration) -> inv.
        float tot = 0.f;
#pragma unroll
        for (int w = 0; w < NWARPS; w++) tot += s_red[r & 1][w];
        const float inv = __frcp_rn(tot);  // unused when i>=L (no NaN stored)

        // 2. Issue stores for row r immediately (drain overlaps step 3).
        if (i < L) {
#pragma unroll
            for (int k = 0; k < 2; k++) {
                float4 o;
                o.x = e_cur[k * 4 + 0] * inv;
                o.y = e_cur[k * 4 + 1] * inv;
                o.z = e_cur[k * 4 + 2] * inv;
                o.w = e_cur[k * 4 + 3] * inv;
                __stcs((float4*)orow + tid + k * THREADS, o);
            }
        } else {  // CTA-uniform
            float4 z = make_float4(0.f, 0.f, 0.f, 0.f);
#pragma unroll
            for (int k = 0; k < 2; k++)
                __stcs((float4*)orow + tid + k * THREADS, z);
        }

        // 3. Compute next row under the store drain; double-buffered s_red.
        if (r + 1 < ROWS_PER_CTA) {
            float ps = compute_row(s_s, rowBase + r + 1, L, tid, e_next);
#pragma unroll
            for (int o = 16; o > 0; o >>= 1)
                ps += __shfl_xor_sync(0xffffffffu, ps, o);
            if (lane == 0) s_red[(r + 1) & 1][warp] = ps;
        }
        __syncthreads();
#pragma unroll
        for (int q = 0; q < 8; q++) e_cur[q] = e_next[q];
    }
}

extern "C" void kernel_launch(void* const* d_in, const int* in_sizes, int n_in,
                              void* d_out, int out_size) {
    const float* logits = (const float*)d_in[0];   // [16, 2048, 1] f32
    const int* seq_len = (const int*)d_in[1];      // [16] i32
    float* out = (float*)d_out;                    // [16, 2048, 2048] f32

    pairwise_softmax_kernel<<<NB * (NT / ROWS_PER_CTA), THREADS>>>(logits, seq_len, out);
}